// round 6
// baseline (speedup 1.0000x reference)
#include <cuda_runtime.h>
#include <cuda_bf16.h>

// Problem constants
#define B 64
#define L 512
#define T 8
#define D 1024
#define C 3
#define N_HOPS 6
#define KSPLIT 4
#define KCHUNK (D / KSPLIT)   // 256
#define LS 8                  // l-splits for attention
#define LCHUNK (L / LS)       // 64
#define NATTN (B * LS)        // 512 attention blocks
#define NLIN (16 * KSPLIT)    // 64 lin blocks  -> total 576 <= 592 (single wave)

// ---------------- device scratch ----------------
__device__ __nv_bfloat16 g_mem[(size_t)B * L * D]; // staged context embeddings (64 MB)
__device__ float g_vec[B * D];                     // current hop vector [B,D]
__device__ float g_lin_partial[KSPLIT * B * D];    // split-K partials of vec@W_lin
__device__ float g_attn_partial[LS * B * D];       // split-L partials of attention
__device__ float g_smb[B * L];                     // s_mem_base = v_loc * (emb . wa1)
__device__ float g_vloc[B * L];                    // location weights
__device__ float g_aw[B * L];                      // alpha * v_loc per hop
__device__ float g_svec[B];                        // vec . w_attn[D:]

// ---------------- kernel 1: precompute v_loc, s_mem_base, stage bf16 memory -----
__global__ void precompute_k(const int* __restrict__ ctx,
                             const int* __restrict__ clen,
                             const int* __restrict__ toff,
                             const float* __restrict__ emb,
                             const float* __restrict__ wattn) {
    int b = blockIdx.x;
    int l = blockIdx.y * 8 + (threadIdx.x >> 5);
    int lane = threadIdx.x & 31;
    int len = clen[b];

    float acc = 0.0f;
    float v = 0.0f;
    if (l < len) {
        int id = ctx[b * L + l];
        const float4* e4 = (const float4*)(emb + (long)id * D);
        const float4* w4 = (const float4*)wattn;
        uint2* dst = (uint2*)(g_mem + (size_t)(b * L + l) * D);
        #pragma unroll
        for (int i = 0; i < 8; i++) {
            float4 e = e4[i * 32 + lane];
            float4 w = w4[i * 32 + lane];
            acc += e.x * w.x + e.y * w.y + e.z * w.z + e.w * w.w;
            union { uint2 u; __nv_bfloat162 h[2]; } pk;
            pk.h[0] = __floats2bfloat162_rn(e.x, e.y);
            pk.h[1] = __floats2bfloat162_rn(e.z, e.w);
            dst[i * 32 + lane] = pk.u;
        }
        #pragma unroll
        for (int o = 16; o > 0; o >>= 1)
            acc += __shfl_xor_sync(0xffffffffu, acc, o);
        v = 1.0f - fabsf((float)(l - toff[b])) / (float)len;
    }
    if (lane == 0) {
        g_vloc[b * L + l] = v;
        g_smb[b * L + l] = v * acc;
    }
}

// ---------------- kernel 2: v_aspect -> g_vec, also g_svec ----------------------
__global__ void vaspect_k(const int* __restrict__ tgt,
                          const int* __restrict__ tlen,
                          const float* __restrict__ emb,
                          const float* __restrict__ wattn) {
    int b = blockIdx.x, t = threadIdx.x;
    int n = tlen[b];
    float4 acc = make_float4(0.f, 0.f, 0.f, 0.f);
    #pragma unroll
    for (int i = 0; i < T; i++) {
        if (i < n) {
            int id = tgt[b * T + i];
            float4 e = ((const float4*)(emb + (long)id * D))[t];
            acc.x += e.x; acc.y += e.y; acc.z += e.z; acc.w += e.w;
        }
    }
    float inv = 1.0f / (float)n;
    acc.x *= inv; acc.y *= inv; acc.z *= inv; acc.w *= inv;
    ((float4*)(g_vec + b * D))[t] = acc;

    float4 w = ((const float4*)(wattn + D))[t];
    float p = acc.x * w.x + acc.y * w.y + acc.z * w.z + acc.w * w.w;
    __shared__ float red[256];
    red[t] = p;
    __syncthreads();
    #pragma unroll
    for (int s = 128; s > 0; s >>= 1) {
        if (t < s) red[t] += red[t + s];
        __syncthreads();
    }
    if (t == 0) g_svec[b] = red[0];
}

// ---------------- softmax core (device inline) ----------------------------------
__device__ __forceinline__ void softmax_core(int b, int t, float svec, int len,
                                             float* red) {
    float sc = (t < len) ? tanhf(g_smb[b * L + t] + svec) : -1e30f;
    red[t] = sc;
    __syncthreads();
    #pragma unroll
    for (int s = 256; s > 0; s >>= 1) {
        if (t < s) red[t] = fmaxf(red[t], red[t + s]);
        __syncthreads();
    }
    float mx = red[0];
    __syncthreads();
    float e = expf(sc - mx);
    red[t] = e;
    __syncthreads();
    #pragma unroll
    for (int s = 256; s > 0; s >>= 1) {
        if (t < s) red[t] += red[t + s];
        __syncthreads();
    }
    float sm = red[0];
    g_aw[b * L + t] = (e / sm) * g_vloc[b * L + t];
}

// ---------------- kernel 3: standalone softmax (hop 0) --------------------------
__global__ void softmax_k(const float* __restrict__ battn,
                          const int* __restrict__ clen) {
    int b = blockIdx.x, t = threadIdx.x;
    __shared__ float red[L];
    softmax_core(b, t, g_svec[b] + battn[0], clen[b], red);
}

// ---------------- bf16x8 FMA helper ---------------------------------------------
__device__ __forceinline__ void fma8(float* acc, float w, const uint4& q) {
    const __nv_bfloat162* h = (const __nv_bfloat162*)&q;
    float2 f0 = __bfloat1622float2(h[0]);
    float2 f1 = __bfloat1622float2(h[1]);
    float2 f2 = __bfloat1622float2(h[2]);
    float2 f3 = __bfloat1622float2(h[3]);
    acc[0] += w * f0.x; acc[1] += w * f0.y;
    acc[2] += w * f1.x; acc[3] += w * f1.y;
    acc[4] += w * f2.x; acc[5] += w * f2.y;
    acc[6] += w * f3.x; acc[7] += w * f3.y;
}

// ---------------- kernel 4: FUSED work: attn partials (bf16 staged) + lin GEMM --
// blocks [0, NATTN): attention; blocks [NATTN, NATTN+NLIN): lin split-K GEMM
__global__ void __launch_bounds__(256, 4) work_k(const int* __restrict__ clen,
                                                 const float* __restrict__ Wlin) {
    __shared__ float sh[16 * 65 + 16 * 64];   // lin tiles; attn reuses front
    int bid = blockIdx.x;
    int tid = threadIdx.x;

    if (bid < NATTN) {
        // ---- attention role: block = (b, ls); 2 row-groups x 128 d-threads ----
        // grp g owns rows [s+4g, s+4g+4) of each 8-row superblock s.
        int b = bid & (B - 1);
        int ls = bid >> 6;
        float* aw = sh;                 // [LCHUNK]
        float* part = sh + LCHUNK;      // [128*8] cross-group reduce buffer
        int l0 = ls * LCHUNK;
        if (tid < LCHUNK) aw[tid] = g_aw[b * L + l0 + tid];
        __syncthreads();

        int len = clen[b];
        int lend = len - l0;
        if (lend > LCHUNK) lend = LCHUNK;
        if (lend < 0) lend = 0;

        int grp = tid >> 7;
        int dt = tid & 127;        // 16B slice of D (8 bf16)
        const uint4* base = (const uint4*)(g_mem + (size_t)(b * L + l0) * D) + dt;

        float acc[8] = {};
        int l = grp * 4;
        // 4 independent 16B loads in flight before any consumption
        #pragma unroll 1
        while (l + 3 < lend) {
            uint4 q0 = base[(l + 0) * 128];
            uint4 q1 = base[(l + 1) * 128];
            uint4 q2 = base[(l + 2) * 128];
            uint4 q3 = base[(l + 3) * 128];
            float w0 = aw[l], w1 = aw[l + 1], w2 = aw[l + 2], w3 = aw[l + 3];
            fma8(acc, w0, q0);
            fma8(acc, w1, q1);
            fma8(acc, w2, q2);
            fma8(acc, w3, q3);
            l += 8;
        }
        #pragma unroll 1
        for (; l < lend; l++) {
            fma8(acc, aw[l], base[l * 128]);
        }

        if (grp == 1) {
            #pragma unroll
            for (int j = 0; j < 8; j++) part[dt * 8 + j] = acc[j];
        }
        __syncthreads();
        if (grp == 0) {
            float* dst = g_attn_partial + ((long)ls * B + b) * D + dt * 8;
            float4 o0, o1;
            o0.x = acc[0] + part[dt * 8 + 0];
            o0.y = acc[1] + part[dt * 8 + 1];
            o0.z = acc[2] + part[dt * 8 + 2];
            o0.w = acc[3] + part[dt * 8 + 3];
            o1.x = acc[4] + part[dt * 8 + 4];
            o1.y = acc[5] + part[dt * 8 + 5];
            o1.z = acc[6] + part[dt * 8 + 6];
            o1.w = acc[7] + part[dt * 8 + 7];
            *(float4*)dst = o0;
            *(float4*)(dst + 4) = o1;
        }
    } else {
        // ---- lin GEMM role: 64x64 tile, split-K 4 (KCHUNK=256) ----
        int lb = bid - NATTN;
        int n0 = (lb & 15) * 64;
        int ks = lb >> 4;
        int kbase = ks * KCHUNK;
        float (*As)[65] = (float(*)[65])sh;
        float (*Bs)[64] = (float(*)[64])(sh + 16 * 65);
        int tx = tid & 15, ty = tid >> 4;

        float acc[4][4] = {};
        #pragma unroll 2
        for (int k0 = 0; k0 < KCHUNK; k0 += 16) {
            {
                int m = tid >> 2;
                int kq = (tid & 3) << 2;
                float4 av = *(const float4*)&g_vec[m * D + kbase + k0 + kq];
                As[kq + 0][m] = av.x;
                As[kq + 1][m] = av.y;
                As[kq + 2][m] = av.z;
                As[kq + 3][m] = av.w;
            }
            {
                int row = tid >> 4;
                int c4 = (tid & 15) << 2;
                float4 bv = *(const float4*)&Wlin[(long)(kbase + k0 + row) * D + n0 + c4];
                *(float4*)&Bs[row][c4] = bv;
            }
            __syncthreads();
            #pragma unroll
            for (int kk = 0; kk < 16; kk++) {
                float a[4], bb[4];
                #pragma unroll
                for (int i = 0; i < 4; i++) a[i] = As[kk][ty * 4 + i];
                float4 bv = *(const float4*)&Bs[kk][tx * 4];
                bb[0] = bv.x; bb[1] = bv.y; bb[2] = bv.z; bb[3] = bv.w;
                #pragma unroll
                for (int i = 0; i < 4; i++)
                    #pragma unroll
                    for (int j = 0; j < 4; j++)
                        acc[i][j] += a[i] * bb[j];
            }
            __syncthreads();
        }
        #pragma unroll
        for (int i = 0; i < 4; i++) {
            int m = ty * 4 + i;
            #pragma unroll
            for (int j = 0; j < 4; j++) {
                g_lin_partial[((long)ks * B + m) * D + n0 + tx * 4 + j] = acc[i][j];
            }
        }
    }
}

// ---------------- combine core: partials -> vec (2 floats per thread) -----------
__device__ __forceinline__ float2 combine_core(int b, int t, const float* blin) {
    int d = t * 2;
    float2 v = *(const float2*)(blin + d);
    #pragma unroll
    for (int ls = 0; ls < LS; ls++) {
        float2 p = *(const float2*)(g_attn_partial + ((long)ls * B + b) * D + d);
        v.x += p.x; v.y += p.y;
    }
    #pragma unroll
    for (int ks = 0; ks < KSPLIT; ks++) {
        float2 p = *(const float2*)(g_lin_partial + ((long)ks * B + b) * D + d);
        v.x += p.x; v.y += p.y;
    }
    *(float2*)(g_vec + b * D + d) = v;
    return v;
}

// ---------------- kernel 5: fused combine + softmax (hops 0..4) -----------------
__global__ void combine_softmax_k(const float* __restrict__ blin,
                                  const float* __restrict__ wattn,
                                  const float* __restrict__ battn,
                                  const int* __restrict__ clen) {
    int b = blockIdx.x, t = threadIdx.x;
    __shared__ float red[L];

    float2 v = combine_core(b, t, blin);

    int d = t * 2;
    float2 w = *(const float2*)(wattn + D + d);
    red[t] = v.x * w.x + v.y * w.y;
    __syncthreads();
    #pragma unroll
    for (int s = 256; s > 0; s >>= 1) {
        if (t < s) red[t] += red[t + s];
        __syncthreads();
    }
    float svec = red[0] + battn[0];
    __syncthreads();

    softmax_core(b, t, svec, clen[b], red);
}

// ---------------- kernel 6: fused combine + output logits (last hop) ------------
__global__ void combine_out_k(const float* __restrict__ blin,
                              const float* __restrict__ Wout,
                              const float* __restrict__ bout,
                              float* __restrict__ out) {
    int b = blockIdx.x, t = threadIdx.x;
    float2 v = combine_core(b, t, blin);

    int d = t * 2;
    float p0 = v.x * Wout[d * C + 0] + v.y * Wout[(d + 1) * C + 0];
    float p1 = v.x * Wout[d * C + 1] + v.y * Wout[(d + 1) * C + 1];
    float p2 = v.x * Wout[d * C + 2] + v.y * Wout[(d + 1) * C + 2];

    __shared__ float r[C][512];
    r[0][t] = p0; r[1][t] = p1; r[2][t] = p2;
    __syncthreads();
    #pragma unroll
    for (int s = 256; s > 0; s >>= 1) {
        if (t < s) {
            r[0][t] += r[0][t + s];
            r[1][t] += r[1][t + s];
            r[2][t] += r[2][t + s];
        }
        __syncthreads();
    }
    if (t < C) out[b * C + t] = r[t][0] + bout[t];
}

// ---------------- launcher -------------------------------------------------------
extern "C" void kernel_launch(void* const* d_in, const int* in_sizes, int n_in,
                              void* d_out, int out_size) {
    const int*   ctx   = (const int*)d_in[0];
    const int*   tgt   = (const int*)d_in[1];
    const int*   clen  = (const int*)d_in[2];
    const int*   tlen  = (const int*)d_in[3];
    const int*   toff  = (const int*)d_in[4];
    const float* emb   = (const float*)d_in[5];
    const float* Wlin  = (const float*)d_in[6];
    const float* blin  = (const float*)d_in[7];
    const float* wattn = (const float*)d_in[8];
    const float* battn = (const float*)d_in[9];
    const float* Wout  = (const float*)d_in[10];
    const float* bout  = (const float*)d_in[11];
    float* out = (float*)d_out;

    precompute_k<<<dim3(B, L / 8), 256>>>(ctx, clen, toff, emb, wattn);
    vaspect_k<<<B, 256>>>(tgt, tlen, emb, wattn);
    softmax_k<<<B, L>>>(battn, clen);

    for (int h = 0; h < N_HOPS; h++) {
        work_k<<<NATTN + NLIN, 256>>>(clen, Wlin);
        if (h < N_HOPS - 1)
            combine_softmax_k<<<B, L>>>(blin, wattn, battn, clen);
        else
            combine_out_k<<<B, L>>>(blin, Wout, bout, out);
    }
}

// round 8
// speedup vs baseline: 1.6163x; 1.6163x over previous
#include <cuda_runtime.h>
#include <cuda_bf16.h>

// Problem constants
#define B 64
#define L 512
#define T 8
#define D 1024
#define C 3
#define N_HOPS 6
#define LS 8
#define LCHUNK 64
#define NATTN (B * LS)

// ---------------- device scratch ----------------
__device__ float g_P[7][4][D];          // projection chains: [k][0]=W^k wa2, [k][1+m]=W^k Wout[:,m]
__device__ float g_c[5][B][L];          // c_k[b,l] = p_k . emb_row
__device__ float g_smb[B][L];           // v_loc * (emb . wa1)
__device__ float g_vloc[B][L];
__device__ float g_vec[B][D];           // v_aspect (vec_0)
__device__ float g_aw6[N_HOPS][B][L];   // alpha*v_loc per hop
__device__ float g_cp[LS][B][6][D];     // phase-C split-L partials (12.6 MB)
__device__ float g_a[6][B][D];          // a_j = attn_out at hop j

__device__ __forceinline__ float dot4(const float4 a, const float4 b) {
    return a.x * b.x + a.y * b.y + a.z * b.z + a.w * b.w;
}

// ---------------- reduction helpers (512-thread blocks) --------------------------
template <int NV>
__device__ __forceinline__ void block_multired(float* v, float* scratch /*16*NV*/,
                                               float* out /*NV*/, int tid) {
    int lane = tid & 31, wid = tid >> 5;
    #pragma unroll
    for (int i = 0; i < NV; i++)
        #pragma unroll
        for (int o = 16; o > 0; o >>= 1)
            v[i] += __shfl_xor_sync(0xffffffffu, v[i], o);
    if (lane == 0)
        #pragma unroll
        for (int i = 0; i < NV; i++) scratch[wid * NV + i] = v[i];
    __syncthreads();
    if (tid < NV) {
        float s = 0.f;
        #pragma unroll
        for (int w = 0; w < 16; w++) s += scratch[w * NV + tid];
        out[tid] = s;
    }
    __syncthreads();
}

__device__ __forceinline__ float block_max512(float v, float* mscr /*33*/, int tid) {
    int lane = tid & 31, wid = tid >> 5;
    #pragma unroll
    for (int o = 16; o > 0; o >>= 1)
        v = fmaxf(v, __shfl_xor_sync(0xffffffffu, v, o));
    if (lane == 0) mscr[wid] = v;
    __syncthreads();
    if (tid < 32) {
        float m = (tid < 16) ? mscr[tid] : -1e30f;
        #pragma unroll
        for (int o = 8; o > 0; o >>= 1)
            m = fmaxf(m, __shfl_xor_sync(0xffffffffu, m, o));
        if (tid == 0) mscr[32] = m;
    }
    __syncthreads();
    float r = mscr[32];
    __syncthreads();
    return r;
}

// ---------------- kernel: init projection chain (k=0) ----------------------------
__global__ void proj_init_k(const float* __restrict__ wattn,
                            const float* __restrict__ Wout) {
    int d = blockIdx.x * 256 + threadIdx.x;
    g_P[0][0][d] = wattn[D + d];
    #pragma unroll
    for (int m = 0; m < C; m++) g_P[0][1 + m][d] = Wout[d * C + m];
}

// ---------------- kernel: one chain step: g_P[k+1][c] = W @ g_P[k][c] -------------
// grid 256, 128 threads (4 warps), warp per output row
__global__ void matvec4_k(const float* __restrict__ W, int k) {
    int r = blockIdx.x * 4 + (threadIdx.x >> 5);
    int lane = threadIdx.x & 31;
    const float4* w4 = (const float4*)(W + (long)r * D);
    float a0 = 0.f, a1 = 0.f, a2 = 0.f, a3 = 0.f;
    #pragma unroll
    for (int i = 0; i < 8; i++) {
        float4 w = w4[i * 32 + lane];
        a0 += dot4(w, ((const float4*)g_P[k][0])[i * 32 + lane]);
        a1 += dot4(w, ((const float4*)g_P[k][1])[i * 32 + lane]);
        a2 += dot4(w, ((const float4*)g_P[k][2])[i * 32 + lane]);
        a3 += dot4(w, ((const float4*)g_P[k][3])[i * 32 + lane]);
    }
    #pragma unroll
    for (int o = 16; o > 0; o >>= 1) {
        a0 += __shfl_xor_sync(0xffffffffu, a0, o);
        a1 += __shfl_xor_sync(0xffffffffu, a1, o);
        a2 += __shfl_xor_sync(0xffffffffu, a2, o);
        a3 += __shfl_xor_sync(0xffffffffu, a3, o);
    }
    if (lane == 0) {
        g_P[k + 1][0][r] = a0;
        g_P[k + 1][1][r] = a1;
        g_P[k + 1][2][r] = a2;
        g_P[k + 1][3][r] = a3;
    }
}

// ---------------- kernel: pass A — per-row dots (wa1, p_0..p_4), vloc, smb -------
// grid (B, L/8), 256 threads, warp per row
__global__ void precomputeA_k(const int* __restrict__ ctx,
                              const int* __restrict__ clen,
                              const int* __restrict__ toff,
                              const float* __restrict__ emb,
                              const float* __restrict__ wattn) {
    int b = blockIdx.x;
    int l = blockIdx.y * 8 + (threadIdx.x >> 5);
    int lane = threadIdx.x & 31;
    int len = clen[b];

    if (l < len) {
        int id = ctx[b * L + l];
        const float4* e4 = (const float4*)(emb + (long)id * D);
        float4 e[8];
        #pragma unroll
        for (int i = 0; i < 8; i++) e[i] = e4[i * 32 + lane];

        float acc[6] = {};
        #pragma unroll
        for (int i = 0; i < 8; i++) {
            acc[0] += dot4(e[i], ((const float4*)wattn)[i * 32 + lane]);
            acc[1] += dot4(e[i], ((const float4*)g_P[0][0])[i * 32 + lane]);
            acc[2] += dot4(e[i], ((const float4*)g_P[1][0])[i * 32 + lane]);
            acc[3] += dot4(e[i], ((const float4*)g_P[2][0])[i * 32 + lane]);
            acc[4] += dot4(e[i], ((const float4*)g_P[3][0])[i * 32 + lane]);
            acc[5] += dot4(e[i], ((const float4*)g_P[4][0])[i * 32 + lane]);
        }
        #pragma unroll
        for (int j = 0; j < 6; j++)
            #pragma unroll
            for (int o = 16; o > 0; o >>= 1)
                acc[j] += __shfl_xor_sync(0xffffffffu, acc[j], o);

        if (lane == 0) {
            float v = 1.0f - fabsf((float)(l - toff[b])) / (float)len;
            g_vloc[b][l] = v;
            g_smb[b][l] = v * acc[0];
            g_c[0][b][l] = acc[1];
            g_c[1][b][l] = acc[2];
            g_c[2][b][l] = acc[3];
            g_c[3][b][l] = acc[4];
            g_c[4][b][l] = acc[5];
        }
    } else if (lane == 0) {
        g_vloc[b][l] = 0.f;
        g_smb[b][l] = 0.f;
        #pragma unroll
        for (int k = 0; k < 5; k++) g_c[k][b][l] = 0.f;
    }
}

// ---------------- kernel: v_aspect -> g_vec --------------------------------------
__global__ void vaspect_k(const int* __restrict__ tgt,
                          const int* __restrict__ tlen,
                          const float* __restrict__ emb) {
    int b = blockIdx.x, t = threadIdx.x;
    int n = tlen[b];
    float4 acc = make_float4(0.f, 0.f, 0.f, 0.f);
    #pragma unroll
    for (int i = 0; i < T; i++) {
        if (i < n) {
            int id = tgt[b * T + i];
            float4 e = ((const float4*)(emb + (long)id * D))[t];
            acc.x += e.x; acc.y += e.y; acc.z += e.z; acc.w += e.w;
        }
    }
    float inv = 1.0f / (float)n;
    acc.x *= inv; acc.y *= inv; acc.z *= inv; acc.w *= inv;
    ((float4*)g_vec[b])[t] = acc;
}

// ---------------- kernel: scalar hop recurrence -> all aw_h -----------------------
// grid B, 512 threads (one per l)
__global__ void scalar_k(const int* __restrict__ clen,
                         const float* __restrict__ blin,
                         const float* __restrict__ battn) {
    int b = blockIdx.x, t = threadIdx.x;
    __shared__ float scr[16 * 12];
    __shared__ float res12[12];
    __shared__ float mscr[33];
    __shared__ float t_arr[6];
    __shared__ float beta[6];
    __shared__ float A[5];

    // t_k^0 = p_k . v0 ; beta_k = p_k . blin   (k = 0..5)
    {
        float vals[12];
        int d = t * 2;
        float2 v0 = *(const float2*)&g_vec[b][d];
        float2 bl = *(const float2*)&blin[d];
        #pragma unroll
        for (int k = 0; k < 6; k++) {
            float2 p = *(const float2*)&g_P[k][0][d];
            vals[k] = p.x * v0.x + p.y * v0.y;
            vals[6 + k] = p.x * bl.x + p.y * bl.y;
        }
        block_multired<12>(vals, scr, res12, t);
        if (t < 6) { t_arr[t] = res12[t]; beta[t] = res12[6 + t]; }
        __syncthreads();
    }

    int len = clen[b];
    bool valid = t < len;
    float smb_l = g_smb[b][t];
    float vloc_l = g_vloc[b][t];
    float cv[5];
    #pragma unroll
    for (int k = 0; k < 5; k++) cv[k] = g_c[k][b][t];
    float bat = battn[0];

    for (int h = 0; h < N_HOPS; h++) {
        float s = t_arr[0];
        float sc = valid ? tanhf(smb_l + s + bat) : -1e30f;
        float mx = block_max512(sc, mscr, t);
        float e = valid ? expf(sc - mx) : 0.f;
        {
            float v1[1] = {e};
            block_multired<1>(v1, scr, res12, t);
        }
        float aw = (e / res12[0]) * vloc_l;
        g_aw6[h][b][t] = aw;

        float pv[5];
        #pragma unroll
        for (int k = 0; k < 5; k++) pv[k] = aw * cv[k];
        block_multired<5>(pv, scr, A, t);

        if (t == 0) {
            #pragma unroll
            for (int k = 0; k < 5; k++)       // ascending: reads t_arr[k+1] pre-update
                t_arr[k] = A[k] + t_arr[k + 1] + beta[k];
        }
        __syncthreads();
    }
}

// ---------------- kernel: pass C — 6-way weighted sums (split L) -----------------
// grid NATTN=512 blocks, 256 threads; block=(b,ls)
__global__ void phaseC_k(const int* __restrict__ ctx,
                         const int* __restrict__ clen,
                         const float* __restrict__ emb) {
    int bid = blockIdx.x;
    int b = bid & (B - 1);
    int ls = bid >> 6;
    int tid = threadIdx.x;
    __shared__ int ids[LCHUNK];
    __shared__ float w[6][LCHUNK];

    int l0 = ls * LCHUNK;
    if (tid < LCHUNK) ids[tid] = ctx[b * L + l0 + tid];
    // FIX (R7 bug): 6*LCHUNK = 384 > 256 threads; must stride
    for (int i = tid; i < 6 * LCHUNK; i += 256) {
        int j = i >> 6, li = i & (LCHUNK - 1);
        w[j][li] = g_aw6[j][b][l0 + li];
    }
    __syncthreads();

    int len = clen[b];
    int lend = len - l0;
    if (lend > LCHUNK) lend = LCHUNK;
    if (lend < 0) lend = 0;

    float4 acc[6] = {};
    const float4* e4 = (const float4*)emb;
    #pragma unroll 4
    for (int i = 0; i < lend; i++) {
        float4 ev = e4[(long)ids[i] * 256 + tid];
        #pragma unroll
        for (int j = 0; j < 6; j++) {
            float wj = w[j][i];
            acc[j].x += wj * ev.x;
            acc[j].y += wj * ev.y;
            acc[j].z += wj * ev.z;
            acc[j].w += wj * ev.w;
        }
    }
    #pragma unroll
    for (int j = 0; j < 6; j++)
        *(float4*)&g_cp[ls][b][j][tid * 4] = acc[j];
}

// ---------------- kernel: combine phase-C partials -> g_a ------------------------
// grid 6*B, 256 threads
__global__ void combineC_k() {
    int bid = blockIdx.x;
    int b = bid & (B - 1);
    int j = bid >> 6;
    int t = threadIdx.x;
    float4 s = make_float4(0.f, 0.f, 0.f, 0.f);
    #pragma unroll
    for (int ls = 0; ls < LS; ls++) {
        float4 p = *(const float4*)&g_cp[ls][b][j][t * 4];
        s.x += p.x; s.y += p.y; s.z += p.z; s.w += p.w;
    }
    *(float4*)&g_a[j][b][t * 4] = s;
}

// ---------------- kernel: final logits -------------------------------------------
// grid B, 512 threads (float2 per thread)
__global__ void logits_k(const float* __restrict__ blin,
                         const float* __restrict__ bout,
                         float* __restrict__ out) {
    int b = blockIdx.x, t = threadIdx.x;
    __shared__ float scr[16 * 3];
    __shared__ float res[3];

    int d = t * 2;
    float2 v0 = *(const float2*)&g_vec[b][d];
    float2 bl = *(const float2*)&blin[d];

    float pm[3] = {};
    #pragma unroll
    for (int m = 0; m < C; m++) {
        #pragma unroll
        for (int j = 0; j < 6; j++) {
            float2 u = *(const float2*)&g_P[5 - j][1 + m][d];
            float2 a = *(const float2*)&g_a[j][b][d];
            pm[m] += u.x * a.x + u.y * a.y;
        }
        float2 u6 = *(const float2*)&g_P[6][1 + m][d];
        pm[m] += u6.x * v0.x + u6.y * v0.y;
        #pragma unroll
        for (int k = 0; k < 6; k++) {
            float2 uk = *(const float2*)&g_P[k][1 + m][d];
            pm[m] += uk.x * bl.x + uk.y * bl.y;
        }
    }
    block_multired<3>(pm, scr, res, t);
    if (t < C) out[b * C + t] = res[t] + bout[t];
}

// ---------------- launcher -------------------------------------------------------
extern "C" void kernel_launch(void* const* d_in, const int* in_sizes, int n_in,
                              void* d_out, int out_size) {
    const int*   ctx   = (const int*)d_in[0];
    const int*   tgt   = (const int*)d_in[1];
    const int*   clen  = (const int*)d_in[2];
    const int*   tlen  = (const int*)d_in[3];
    const int*   toff  = (const int*)d_in[4];
    const float* emb   = (const float*)d_in[5];
    const float* Wlin  = (const float*)d_in[6];
    const float* blin  = (const float*)d_in[7];
    const float* wattn = (const float*)d_in[8];
    const float* battn = (const float*)d_in[9];
    const float* Wout  = (const float*)d_in[10];
    const float* bout  = (const float*)d_in[11];
    float* out = (float*)d_out;

    proj_init_k<<<4, 256>>>(wattn, Wout);
    for (int k = 0; k < 6; k++)
        matvec4_k<<<256, 128>>>(Wlin, k);

    vaspect_k<<<B, 256>>>(tgt, tlen, emb);
    precomputeA_k<<<dim3(B, L / 8), 256>>>(ctx, clen, toff, emb, wattn);
    scalar_k<<<B, 512>>>(clen, blin, battn);
    phaseC_k<<<NATTN, 256>>>(ctx, clen, emb);
    combineC_k<<<6 * B, 256>>>();
    logits_k<<<B, 512>>>(blin, bout, out);
}

// round 9
// speedup vs baseline: 1.7955x; 1.1109x over previous
#include <cuda_runtime.h>
#include <cuda_bf16.h>

// Problem constants
#define B 64
#define L 512
#define T 8
#define D 1024
#define C 3
#define N_HOPS 6
#define LS 8
#define LCHUNK 64
#define NATTN (B * LS)

// ---------------- device scratch ----------------
__device__ float g_P[7][4][D];          // projection chains: [k][0]=W^k wa2, [k][1+m]=W^k Wout[:,m]
__device__ float g_c[5][B][L];          // c_k[b,l] = p_k . emb_row
__device__ float g_smb[B][L];           // v_loc * (emb . wa1)
__device__ float g_vloc[B][L];
__device__ float g_vec[B][D];           // v_aspect (vec_0)
__device__ float g_aw6[N_HOPS][B][L];   // alpha*v_loc per hop
__device__ float g_cp[LS][B][6][D];     // phase-C split-L partials (12.6 MB)
__device__ float g_a[6][B][D];          // a_j = attn_out at hop j

__device__ __forceinline__ float dot4(const float4 a, const float4 b) {
    return a.x * b.x + a.y * b.y + a.z * b.z + a.w * b.w;
}

// ---------------- reduction helpers (512-thread blocks) --------------------------
template <int NV>
__device__ __forceinline__ void block_multired(float* v, float* scratch /*16*NV*/,
                                               float* out /*NV*/, int tid) {
    int lane = tid & 31, wid = tid >> 5;
    #pragma unroll
    for (int i = 0; i < NV; i++)
        #pragma unroll
        for (int o = 16; o > 0; o >>= 1)
            v[i] += __shfl_xor_sync(0xffffffffu, v[i], o);
    if (lane == 0)
        #pragma unroll
        for (int i = 0; i < NV; i++) scratch[wid * NV + i] = v[i];
    __syncthreads();
    if (tid < NV) {
        float s = 0.f;
        #pragma unroll
        for (int w = 0; w < 16; w++) s += scratch[w * NV + tid];
        out[tid] = s;
    }
    __syncthreads();
}

__device__ __forceinline__ float block_max512(float v, float* mscr /*33*/, int tid) {
    int lane = tid & 31, wid = tid >> 5;
    #pragma unroll
    for (int o = 16; o > 0; o >>= 1)
        v = fmaxf(v, __shfl_xor_sync(0xffffffffu, v, o));
    if (lane == 0) mscr[wid] = v;
    __syncthreads();
    if (tid < 32) {
        float m = (tid < 16) ? mscr[tid] : -1e30f;
        #pragma unroll
        for (int o = 8; o > 0; o >>= 1)
            m = fmaxf(m, __shfl_xor_sync(0xffffffffu, m, o));
        if (tid == 0) mscr[32] = m;
    }
    __syncthreads();
    float r = mscr[32];
    __syncthreads();
    return r;
}

// ---------------- kernel: init projection chain (k=0) ----------------------------
__global__ void proj_init_k(const float* __restrict__ wattn,
                            const float* __restrict__ Wout) {
    int d = blockIdx.x * 256 + threadIdx.x;
    g_P[0][0][d] = wattn[D + d];
    #pragma unroll
    for (int m = 0; m < C; m++) g_P[0][1 + m][d] = Wout[d * C + m];
}

// ---------------- kernel: one chain step: g_P[k+1][c] = W @ g_P[k][c] -------------
// grid 1024 (block per output row), 256 threads (float4 of the row each)
__global__ void matvec4_k(const float* __restrict__ W, int k) {
    int r = blockIdx.x;
    int t = threadIdx.x;
    __shared__ float scr[8 * 4];

    float4 w = ((const float4*)(W + (long)r * D))[t];
    float a[4];
    #pragma unroll
    for (int c = 0; c < 4; c++)
        a[c] = dot4(w, ((const float4*)g_P[k][c])[t]);

    #pragma unroll
    for (int c = 0; c < 4; c++)
        #pragma unroll
        for (int o = 16; o > 0; o >>= 1)
            a[c] += __shfl_xor_sync(0xffffffffu, a[c], o);

    int lane = t & 31, wid = t >> 5;
    if (lane == 0)
        #pragma unroll
        for (int c = 0; c < 4; c++) scr[wid * 4 + c] = a[c];
    __syncthreads();
    if (t < 4) {
        float s = 0.f;
        #pragma unroll
        for (int w8 = 0; w8 < 8; w8++) s += scr[w8 * 4 + t];
        g_P[k + 1][t][r] = s;
    }
}

// ---------------- kernel: pass A — per-row dots (wa1, p_0..p_4), vloc, smb -------
// grid (B, L/8), 256 threads, warp per row
__global__ void precomputeA_k(const int* __restrict__ ctx,
                              const int* __restrict__ clen,
                              const int* __restrict__ toff,
                              const float* __restrict__ emb,
                              const float* __restrict__ wattn) {
    int b = blockIdx.x;
    int l = blockIdx.y * 8 + (threadIdx.x >> 5);
    int lane = threadIdx.x & 31;
    int len = clen[b];

    if (l < len) {
        int id = ctx[b * L + l];
        const float4* e4 = (const float4*)(emb + (long)id * D);
        float4 e[8];
        #pragma unroll
        for (int i = 0; i < 8; i++) e[i] = e4[i * 32 + lane];

        float acc[6] = {};
        #pragma unroll
        for (int i = 0; i < 8; i++) {
            acc[0] += dot4(e[i], ((const float4*)wattn)[i * 32 + lane]);
            acc[1] += dot4(e[i], ((const float4*)g_P[0][0])[i * 32 + lane]);
            acc[2] += dot4(e[i], ((const float4*)g_P[1][0])[i * 32 + lane]);
            acc[3] += dot4(e[i], ((const float4*)g_P[2][0])[i * 32 + lane]);
            acc[4] += dot4(e[i], ((const float4*)g_P[3][0])[i * 32 + lane]);
            acc[5] += dot4(e[i], ((const float4*)g_P[4][0])[i * 32 + lane]);
        }
        #pragma unroll
        for (int j = 0; j < 6; j++)
            #pragma unroll
            for (int o = 16; o > 0; o >>= 1)
                acc[j] += __shfl_xor_sync(0xffffffffu, acc[j], o);

        if (lane == 0) {
            float v = 1.0f - fabsf((float)(l - toff[b])) / (float)len;
            g_vloc[b][l] = v;
            g_smb[b][l] = v * acc[0];
            g_c[0][b][l] = acc[1];
            g_c[1][b][l] = acc[2];
            g_c[2][b][l] = acc[3];
            g_c[3][b][l] = acc[4];
            g_c[4][b][l] = acc[5];
        }
    } else if (lane == 0) {
        g_vloc[b][l] = 0.f;
        g_smb[b][l] = 0.f;
        #pragma unroll
        for (int k = 0; k < 5; k++) g_c[k][b][l] = 0.f;
    }
}

// ---------------- kernel: v_aspect -> g_vec --------------------------------------
__global__ void vaspect_k(const int* __restrict__ tgt,
                          const int* __restrict__ tlen,
                          const float* __restrict__ emb) {
    int b = blockIdx.x, t = threadIdx.x;
    int n = tlen[b];
    float4 acc = make_float4(0.f, 0.f, 0.f, 0.f);
    #pragma unroll
    for (int i = 0; i < T; i++) {
        if (i < n) {
            int id = tgt[b * T + i];
            float4 e = ((const float4*)(emb + (long)id * D))[t];
            acc.x += e.x; acc.y += e.y; acc.z += e.z; acc.w += e.w;
        }
    }
    float inv = 1.0f / (float)n;
    acc.x *= inv; acc.y *= inv; acc.z *= inv; acc.w *= inv;
    ((float4*)g_vec[b])[t] = acc;
}

// ---------------- kernel: scalar hop recurrence -> all aw_h -----------------------
// grid B, 512 threads (one per l)
__global__ void scalar_k(const int* __restrict__ clen,
                         const float* __restrict__ blin,
                         const float* __restrict__ battn) {
    int b = blockIdx.x, t = threadIdx.x;
    __shared__ float scr[16 * 12];
    __shared__ float res12[12];
    __shared__ float mscr[33];
    __shared__ float t_arr[6];
    __shared__ float beta[6];
    __shared__ float A[5];

    // t_k^0 = p_k . v0 ; beta_k = p_k . blin   (k = 0..5)
    {
        float vals[12];
        int d = t * 2;
        float2 v0 = *(const float2*)&g_vec[b][d];
        float2 bl = *(const float2*)&blin[d];
        #pragma unroll
        for (int k = 0; k < 6; k++) {
            float2 p = *(const float2*)&g_P[k][0][d];
            vals[k] = p.x * v0.x + p.y * v0.y;
            vals[6 + k] = p.x * bl.x + p.y * bl.y;
        }
        block_multired<12>(vals, scr, res12, t);
        if (t < 6) { t_arr[t] = res12[t]; beta[t] = res12[6 + t]; }
        __syncthreads();
    }

    int len = clen[b];
    bool valid = t < len;
    float smb_l = g_smb[b][t];
    float vloc_l = g_vloc[b][t];
    float cv[5];
    #pragma unroll
    for (int k = 0; k < 5; k++) cv[k] = g_c[k][b][t];
    float bat = battn[0];

    for (int h = 0; h < N_HOPS; h++) {
        float s = t_arr[0];
        float sc = valid ? tanhf(smb_l + s + bat) : -1e30f;
        float mx = block_max512(sc, mscr, t);
        float e = valid ? expf(sc - mx) : 0.f;
        {
            float v1[1] = {e};
            block_multired<1>(v1, scr, res12, t);
        }
        float aw = (e / res12[0]) * vloc_l;
        g_aw6[h][b][t] = aw;

        float pv[5];
        #pragma unroll
        for (int k = 0; k < 5; k++) pv[k] = aw * cv[k];
        block_multired<5>(pv, scr, A, t);

        if (t == 0) {
            #pragma unroll
            for (int k = 0; k < 5; k++)       // ascending: reads t_arr[k+1] pre-update
                t_arr[k] = A[k] + t_arr[k + 1] + beta[k];
        }
        __syncthreads();
    }
}

// ---------------- kernel: pass C — 6-way weighted sums (split L) -----------------
// grid NATTN=512 blocks, 256 threads; block=(b,ls)
__global__ void phaseC_k(const int* __restrict__ ctx,
                         const int* __restrict__ clen,
                         const float* __restrict__ emb) {
    int bid = blockIdx.x;
    int b = bid & (B - 1);
    int ls = bid >> 6;
    int tid = threadIdx.x;
    __shared__ int ids[LCHUNK];
    __shared__ float w[6][LCHUNK];

    int l0 = ls * LCHUNK;
    if (tid < LCHUNK) ids[tid] = ctx[b * L + l0 + tid];
    for (int i = tid; i < 6 * LCHUNK; i += 256) {
        int j = i >> 6, li = i & (LCHUNK - 1);
        w[j][li] = g_aw6[j][b][l0 + li];
    }
    __syncthreads();

    int len = clen[b];
    int lend = len - l0;
    if (lend > LCHUNK) lend = LCHUNK;
    if (lend < 0) lend = 0;

    float4 acc[6] = {};
    const float4* e4 = (const float4*)emb;
    #pragma unroll 4
    for (int i = 0; i < lend; i++) {
        float4 ev = e4[(long)ids[i] * 256 + tid];
        #pragma unroll
        for (int j = 0; j < 6; j++) {
            float wj = w[j][i];
            acc[j].x += wj * ev.x;
            acc[j].y += wj * ev.y;
            acc[j].z += wj * ev.z;
            acc[j].w += wj * ev.w;
        }
    }
    #pragma unroll
    for (int j = 0; j < 6; j++)
        *(float4*)&g_cp[ls][b][j][tid * 4] = acc[j];
}

// ---------------- kernel: combine phase-C partials -> g_a ------------------------
// grid 6*B, 256 threads
__global__ void combineC_k() {
    int bid = blockIdx.x;
    int b = bid & (B - 1);
    int j = bid >> 6;
    int t = threadIdx.x;
    float4 s = make_float4(0.f, 0.f, 0.f, 0.f);
    #pragma unroll
    for (int ls = 0; ls < LS; ls++) {
        float4 p = *(const float4*)&g_cp[ls][b][j][t * 4];
        s.x += p.x; s.y += p.y; s.z += p.z; s.w += p.w;
    }
    *(float4*)&g_a[j][b][t * 4] = s;
}

// ---------------- kernel: final logits -------------------------------------------
// grid B, 512 threads (float2 per thread)
__global__ void logits_k(const float* __restrict__ blin,
                         const float* __restrict__ bout,
                         float* __restrict__ out) {
    int b = blockIdx.x, t = threadIdx.x;
    __shared__ float scr[16 * 3];
    __shared__ float res[3];

    int d = t * 2;
    float2 v0 = *(const float2*)&g_vec[b][d];
    float2 bl = *(const float2*)&blin[d];

    float pm[3] = {};
    #pragma unroll
    for (int m = 0; m < C; m++) {
        #pragma unroll
        for (int j = 0; j < 6; j++) {
            float2 u = *(const float2*)&g_P[5 - j][1 + m][d];
            float2 a = *(const float2*)&g_a[j][b][d];
            pm[m] += u.x * a.x + u.y * a.y;
        }
        float2 u6 = *(const float2*)&g_P[6][1 + m][d];
        pm[m] += u6.x * v0.x + u6.y * v0.y;
        #pragma unroll
        for (int k = 0; k < 6; k++) {
            float2 uk = *(const float2*)&g_P[k][1 + m][d];
            pm[m] += uk.x * bl.x + uk.y * bl.y;
        }
    }
    block_multired<3>(pm, scr, res, t);
    if (t < C) out[b * C + t] = res[t] + bout[t];
}

// ---------------- launcher -------------------------------------------------------
extern "C" void kernel_launch(void* const* d_in, const int* in_sizes, int n_in,
                              void* d_out, int out_size) {
    const int*   ctx   = (const int*)d_in[0];
    const int*   tgt   = (const int*)d_in[1];
    const int*   clen  = (const int*)d_in[2];
    const int*   tlen  = (const int*)d_in[3];
    const int*   toff  = (const int*)d_in[4];
    const float* emb   = (const float*)d_in[5];
    const float* Wlin  = (const float*)d_in[6];
    const float* blin  = (const float*)d_in[7];
    const float* wattn = (const float*)d_in[8];
    const float* battn = (const float*)d_in[9];
    const float* Wout  = (const float*)d_in[10];
    const float* bout  = (const float*)d_in[11];
    float* out = (float*)d_out;

    proj_init_k<<<4, 256>>>(wattn, Wout);
    for (int k = 0; k < 6; k++)
        matvec4_k<<<1024, 256>>>(Wlin, k);

    vaspect_k<<<B, 256>>>(tgt, tlen, emb);
    precomputeA_k<<<dim3(B, L / 8), 256>>>(ctx, clen, toff, emb, wattn);
    scalar_k<<<B, 512>>>(clen, blin, battn);
    phaseC_k<<<NATTN, 256>>>(ctx, clen, emb);
    combineC_k<<<6 * B, 256>>>();
    logits_k<<<B, 512>>>(blin, bout, out);
}